// round 8
// baseline (speedup 1.0000x reference)
#include <cuda_runtime.h>
#include <cuda_bf16.h>

// Morphology dilation2d, diamond 5x5, depthwise, C=3, N=32, H=W=512.
// out(y,x) = 1.0 iff ANY input in the diamond neighborhood is > 0.
//
// Inputs are nonnegative fp32 in [0,1): any nonzero value is a normal float,
// so its HIGH 16 BITS are nonzero. We OR only high halves, packing TWO
// columns per 32-bit register (PRMT). Each thread owns 8 columns (4 packed
// words), so halo loads and shift work amortize over twice the data.
// Bit-exact vs the conv+threshold reference.

#define IMG_W 512
#define IMG_H 512
#define N_IMGS 96            // 32 * 3 independent planes
#define STRIP 16             // output rows per block
#define NROWS (STRIP + 4)    // input rows touched per block
#define TPB   64             // threads per block; each owns 8 columns

struct RowRaw { uint4 b0; uint4 b1; uint2 a; uint2 c; };

__device__ __forceinline__ RowRaw load_row(const unsigned* __restrict__ base,
                                           int y, int x0, int a_off, int c_off) {
    int yc = min(max(y, 0), IMG_H - 1);   // clamp; bogus rows masked later
    const unsigned* __restrict__ row = base + yc * IMG_W;
    RowRaw r;
    r.b0 = *reinterpret_cast<const uint4*>(row + x0);
    r.b1 = *reinterpret_cast<const uint4*>(row + x0 + 4);
    r.a  = *reinterpret_cast<const uint2*>(row + a_off);
    r.c  = *reinterpret_cast<const uint2*>(row + c_off);
    return r;
}

__global__ __launch_bounds__(TPB, 16)
void dilate_diamond5_kernel(const float* __restrict__ xf, float* __restrict__ outf) {
    const int img = blockIdx.y;
    const int y0  = blockIdx.x * STRIP;
    const int tid = threadIdx.x;          // 0..63, each owns 8 columns
    const int x0  = tid << 3;

    const unsigned* __restrict__ in =
        reinterpret_cast<const unsigned*>(xf) + (size_t)img * IMG_H * IMG_W;
    float* __restrict__ op = outf + (size_t)img * IMG_H * IMG_W;

    // Clamped halo addresses; contributions killed via masks (branch-free).
    const int a_off = tid ? x0 - 2 : 0;
    const int c_off = (tid < TPB - 1) ? x0 + 8 : IMG_W - 8;
    const unsigned lm   = tid ? ~0u : 0u;
    const unsigned rm   = (tid < TPB - 1) ? ~0u : 0u;
    const unsigned topm = y0 ? ~0u : 0u;
    const unsigned botm = (y0 != IMG_H - STRIP) ? ~0u : 0u;

    // Rotating accumulators: acc[j%5][w] = OR of taps for output row j,
    // 4 packed words per row (2 columns per word, low 16 = lower column).
    unsigned acc[5][4];
#pragma unroll
    for (int s = 0; s < 5; ++s) {
        acc[s][0] = 0u; acc[s][1] = 0u; acc[s][2] = 0u; acc[s][3] = 0u;
    }

    // Depth-2 software pipeline.
    RowRaw r0 = load_row(in, y0 - 2, x0, a_off, c_off);
    RowRaw r1 = load_row(in, y0 - 1, x0, a_off, c_off);

#pragma unroll
    for (int i = 0; i < NROWS; ++i) {
        RowRaw r2 = r1;
        if (i < NROWS - 2)   // compile-time under full unroll
            r2 = load_row(in, y0 + i, x0, a_off, c_off);

        // Pack high halves: 2 cols per word.
        unsigned M0 = __byte_perm(r0.b0.x, r0.b0.y, 0x7632);      // cols 0,1
        unsigned M1 = __byte_perm(r0.b0.z, r0.b0.w, 0x7632);      // cols 2,3
        unsigned M2 = __byte_perm(r0.b1.x, r0.b1.y, 0x7632);      // cols 4,5
        unsigned M3 = __byte_perm(r0.b1.z, r0.b1.w, 0x7632);      // cols 6,7
        unsigned mA = __byte_perm(r0.a.x,  r0.a.y,  0x7632) & lm; // cols -2,-1
        unsigned mC = __byte_perm(r0.c.x,  r0.c.y,  0x7632) & rm; // cols 8,9
        if (i < 2) {
            M0 &= topm; M1 &= topm; M2 &= topm; M3 &= topm; mA &= topm; mC &= topm;
        }
        if (i >= NROWS - 2) {
            M0 &= botm; M1 &= botm; M2 &= botm; M3 &= botm; mA &= botm; mC &= botm;
        }

        // One-column shifts via 16-bit funnels; two-column shifts are free.
        const unsigned S0 = __funnelshift_r(mA, M0, 16);  // cols -1,0
        const unsigned S1 = __funnelshift_r(M0, M1, 16);  // cols 1,2
        const unsigned S2 = __funnelshift_r(M1, M2, 16);  // cols 3,4
        const unsigned S3 = __funnelshift_r(M2, M3, 16);  // cols 5,6
        const unsigned S4 = __funnelshift_r(M3, mC, 16);  // cols 7,8

        const unsigned h3_0 = M0 | S0 | S1;               // width-3 OR
        const unsigned h3_1 = M1 | S1 | S2;
        const unsigned h3_2 = M2 | S2 | S3;
        const unsigned h3_3 = M3 | S3 | S4;
        const unsigned h5_0 = h3_0 | mA | M1;             // width-5 OR
        const unsigned h5_1 = h3_1 | M0 | M2;
        const unsigned h5_2 = h3_2 | M1 | M3;
        const unsigned h5_3 = h3_3 | M2 | mC;

        const int sF = i % 5;          // fresh:  out row j=i   (H1)
        const int s1 = (i + 4) % 5;    // out row j=i-1 (h3)
        const int s2 = (i + 3) % 5;    // out row j=i-2 (h5)
        const int s3 = (i + 2) % 5;    // out row j=i-3 (h3)
        const int sR = (i + 1) % 5;    // retire: out row j=i-4 (+H1 inline)

        if (i >= 4) {
            const unsigned o0 = acc[sR][0] | M0;
            const unsigned o1 = acc[sR][1] | M1;
            const unsigned o2 = acc[sR][2] | M2;
            const unsigned o3 = acc[sR][3] | M3;
            float4 fa, fb;
            fa.x = (o0 & 0x0000FFFFu) ? 1.f : 0.f;
            fa.y = (o0 & 0xFFFF0000u) ? 1.f : 0.f;
            fa.z = (o1 & 0x0000FFFFu) ? 1.f : 0.f;
            fa.w = (o1 & 0xFFFF0000u) ? 1.f : 0.f;
            fb.x = (o2 & 0x0000FFFFu) ? 1.f : 0.f;
            fb.y = (o2 & 0xFFFF0000u) ? 1.f : 0.f;
            fb.z = (o3 & 0x0000FFFFu) ? 1.f : 0.f;
            fb.w = (o3 & 0xFFFF0000u) ? 1.f : 0.f;
            float* orow = op + (y0 + i - 4) * IMG_W + x0;
            __stcs(reinterpret_cast<float4*>(orow),     fa);
            __stcs(reinterpret_cast<float4*>(orow + 4), fb);
        }

        acc[sF][0] = M0;    acc[sF][1] = M1;    acc[sF][2] = M2;    acc[sF][3] = M3;
        acc[s1][0] |= h3_0; acc[s1][1] |= h3_1; acc[s1][2] |= h3_2; acc[s1][3] |= h3_3;
        acc[s2][0] |= h5_0; acc[s2][1] |= h5_1; acc[s2][2] |= h5_2; acc[s2][3] |= h5_3;
        acc[s3][0] |= h3_0; acc[s3][1] |= h3_1; acc[s3][2] |= h3_2; acc[s3][3] |= h3_3;

        r0 = r1;
        r1 = r2;
    }
}

extern "C" void kernel_launch(void* const* d_in, const int* in_sizes, int n_in,
                              void* d_out, int out_size) {
    (void)in_sizes; (void)n_in; (void)out_size;
    const float* x = (const float*)d_in[0];
    float* out = (float*)d_out;
    dim3 grid(IMG_H / STRIP, N_IMGS);
    dilate_diamond5_kernel<<<grid, TPB>>>(x, out);
}

// round 9
// speedup vs baseline: 1.1500x; 1.1500x over previous
#include <cuda_runtime.h>
#include <cuda_bf16.h>

// Morphology dilation2d, diamond 5x5, depthwise, C=3, N=32, H=W=512.
// out(y,x) = 1.0 iff ANY input in the diamond neighborhood is > 0.
//
// Inputs are nonnegative fp32 in [0,1): any nonzero value is a normal float,
// so its HIGH 16 BITS are nonzero. We OR only high halves, packing TWO
// columns per 32-bit register (PRMT), reducing the diamond to funnel shifts
// + 3-input LOP3 ORs. Depth-3 software pipeline on the row loads.
// Bit-exact vs the conv+threshold reference.

#define IMG_W 512
#define IMG_H 512
#define N_IMGS 96            // 32 * 3 independent planes
#define STRIP 16             // output rows per block
#define NROWS (STRIP + 4)    // input rows touched per block

struct RowRaw { uint4 b; uint2 a; uint2 c; };

__device__ __forceinline__ RowRaw load_row(const unsigned* __restrict__ base,
                                           int y, int x0, int a_off, int c_off) {
    int yc = min(max(y, 0), IMG_H - 1);   // clamp; bogus rows masked later
    const unsigned* __restrict__ row = base + yc * IMG_W;
    RowRaw r;
    r.b = *reinterpret_cast<const uint4*>(row + x0);
    r.a = *reinterpret_cast<const uint2*>(row + a_off);
    r.c = *reinterpret_cast<const uint2*>(row + c_off);
    return r;
}

__global__ __launch_bounds__(128, 10)
void dilate_diamond5_kernel(const float* __restrict__ xf, float* __restrict__ outf) {
    const int img = blockIdx.y;
    const int y0  = blockIdx.x * STRIP;
    const int tid = threadIdx.x;          // 0..127, each owns 4 columns
    const int x0  = tid << 2;

    const unsigned* __restrict__ in =
        reinterpret_cast<const unsigned*>(xf) + (size_t)img * IMG_H * IMG_W;
    float* __restrict__ op = outf + (size_t)img * IMG_H * IMG_W;

    // Clamped halo addresses; contributions killed via masks (branch-free).
    const int a_off = tid ? x0 - 2 : 0;
    const int c_off = (tid < 127) ? x0 + 4 : IMG_W - 8;
    const unsigned lm   = tid ? ~0u : 0u;
    const unsigned rm   = (tid < 127) ? ~0u : 0u;
    const unsigned topm = y0 ? ~0u : 0u;
    const unsigned botm = (y0 != IMG_H - STRIP) ? ~0u : 0u;

    // Rotating accumulators: acc[j%5][w] = OR of taps for output row j,
    // packed 2 columns per word (low 16 = lower column).
    unsigned acc[5][2];
#pragma unroll
    for (int s = 0; s < 5; ++s) { acc[s][0] = 0u; acc[s][1] = 0u; }

    // Depth-3 software pipeline: rows for iterations i, i+1, i+2 in flight.
    RowRaw r0 = load_row(in, y0 - 2, x0, a_off, c_off);
    RowRaw r1 = load_row(in, y0 - 1, x0, a_off, c_off);
    RowRaw r2 = load_row(in, y0,     x0, a_off, c_off);

#pragma unroll
    for (int i = 0; i < NROWS; ++i) {
        RowRaw r3 = r2;
        if (i < NROWS - 3)   // compile-time under full unroll
            r3 = load_row(in, y0 + 1 + i, x0, a_off, c_off);

        // Pack high halves: lanes = columns, 2 cols per word.
        unsigned M0 = __byte_perm(r0.b.x, r0.b.y, 0x7632);       // cols 0,1
        unsigned M1 = __byte_perm(r0.b.z, r0.b.w, 0x7632);       // cols 2,3
        unsigned mA = __byte_perm(r0.a.x, r0.a.y, 0x7632) & lm;  // cols -2,-1
        unsigned mC = __byte_perm(r0.c.x, r0.c.y, 0x7632) & rm;  // cols 4,5
        if (i < 2)          { M0 &= topm; M1 &= topm; mA &= topm; mC &= topm; }
        if (i >= NROWS - 2) { M0 &= botm; M1 &= botm; mA &= botm; mC &= botm; }

        // One-column shifts via 16-bit funnels; two-column shifts are free.
        const unsigned L10 = __funnelshift_r(mA, M0, 16);  // cols -1,0
        const unsigned R10 = __funnelshift_r(M0, M1, 16);  // cols 1,2
        const unsigned R11 = __funnelshift_r(M1, mC, 16);  // cols 3,4
        const unsigned h30 = M0 | L10 | R10;               // width-3 OR
        const unsigned h31 = M1 | R10 | R11;
        const unsigned h50 = h30 | mA | M1;                // width-5 OR
        const unsigned h51 = h31 | M0 | mC;

        const int sF = i % 5;          // fresh:  out row j=i   (H1)
        const int s1 = (i + 4) % 5;    // out row j=i-1 (h3)
        const int s2 = (i + 3) % 5;    // out row j=i-2 (h5)
        const int s3 = (i + 2) % 5;    // out row j=i-3 (h3)
        const int sR = (i + 1) % 5;    // retire: out row j=i-4 (+H1 inline)

        if (i >= 4) {
            const unsigned o0 = acc[sR][0] | M0;
            const unsigned o1 = acc[sR][1] | M1;
            float4 f;
            f.x = (o0 & 0x0000FFFFu) ? 1.f : 0.f;
            f.y = (o0 & 0xFFFF0000u) ? 1.f : 0.f;
            f.z = (o1 & 0x0000FFFFu) ? 1.f : 0.f;
            f.w = (o1 & 0xFFFF0000u) ? 1.f : 0.f;
            __stcs(reinterpret_cast<float4*>(op + (y0 + i - 4) * IMG_W + x0), f);
        }

        acc[sF][0] = M0;    acc[sF][1] = M1;
        acc[s1][0] |= h30;  acc[s1][1] |= h31;
        acc[s2][0] |= h50;  acc[s2][1] |= h51;
        acc[s3][0] |= h30;  acc[s3][1] |= h31;

        r0 = r1;
        r1 = r2;
        r2 = r3;
    }
}

extern "C" void kernel_launch(void* const* d_in, const int* in_sizes, int n_in,
                              void* d_out, int out_size) {
    (void)in_sizes; (void)n_in; (void)out_size;
    const float* x = (const float*)d_in[0];
    float* out = (float*)d_out;
    dim3 grid(IMG_H / STRIP, N_IMGS);
    dilate_diamond5_kernel<<<grid, 128>>>(x, out);
}